// round 6
// baseline (speedup 1.0000x reference)
#include <cuda_runtime.h>
#include <math.h>

// Problem constants
#define NB 64
#define NF 36
#define NQ 100
#define NQP 101                         // ben smem stride (conflict-free)
#define NT 20
#define NC 92
#define NCP 93                          // logits smem stride
#define NQUERY (NB * NF * NQ)          // 230400
#define NINST  (NB * NF)               // 2304
#define COST_ELEMS (NQUERY * NT)       // 4608000
#define IDX_ELEMS  (NINST * NT)        // 46080
#define FULLW 0xffffffffu

__device__ __forceinline__ void merge2(float& b1, int& i1, float& b2,
                                       float ob1, int oi1, float ob2)
{
    const bool aw = (b1 > ob1) || (b1 == ob1 && i1 < oi1);
    const float lose = aw ? ob1 : b1;
    b2 = fmaxf(lose, fmaxf(b2, ob2));
    if (!aw) { b1 = ob1; i1 = oi1; }
}

// ---------------------------------------------------------------------------
// Kernel A: cost tensor (R3 structure). Block = one (b,f) frame; thread q
// computes query q; logits staged in smem with coalesced float4 loads.
// ---------------------------------------------------------------------------
__global__ __launch_bounds__(128) void cost_kernel(
        const float* __restrict__ logits,
        const float* __restrict__ pboxes,
        const int*   __restrict__ tlabels,
        const float* __restrict__ tboxes,
        float* __restrict__ cost)
{
    const int inst = blockIdx.x;          // b*36 + f
    const int b = inst / NF;
    const int f = inst - b * NF;
    const int tid = threadIdx.x;

    __shared__ float sh[NQ * NCP];        // 37.2 KB
    __shared__ float4 stbc[NT];
    __shared__ float4 stbx[NT];
    __shared__ float  sarea[NT];
    __shared__ int    slab[NT];

    const float4* lg4 = (const float4*)(logits + ((size_t)b * (NF * NQ) + f * NQ) * NC);
    #pragma unroll 4
    for (int i = tid; i < NQ * (NC / 4); i += 128) {
        const float4 v = lg4[i];
        const int q  = i / 23;
        const int c4 = (i - q * 23) * 4;
        float* dst = &sh[q * NCP + c4];
        dst[0] = v.x; dst[1] = v.y; dst[2] = v.z; dst[3] = v.w;
    }

    if (tid < NT) {
        const size_t tb_ = (size_t)(f * NB + b) * NT + tid;
        const float4 tb = ((const float4*)tboxes)[tb_];
        stbc[tid] = tb;
        const float x0 = tb.x - 0.5f * tb.z, y0 = tb.y - 0.5f * tb.w;
        const float x1 = tb.x + 0.5f * tb.z, y1 = tb.y + 0.5f * tb.w;
        stbx[tid]  = make_float4(x0, y0, x1, y1);
        sarea[tid] = (x1 - x0) * (y1 - y0);
        slab[tid]  = tlabels[tb_];
    }
    __syncthreads();

    float res[NT];
    const int q = tid;
    if (q < NQ) {
        const float* row = &sh[q * NCP];

        float s = 0.0f;
        #pragma unroll 4
        for (int c = 0; c < NC; ++c) s += __expf(row[c]);
        const float rs = __fdividef(1.0f, s);

        const float4 pb = *(const float4*)(pboxes + ((size_t)b * (NF * NQ) + f * NQ + q) * 4);
        const float px0 = pb.x - 0.5f * pb.z;
        const float py0 = pb.y - 0.5f * pb.w;
        const float px1 = pb.x + 0.5f * pb.z;
        const float py1 = pb.y + 0.5f * pb.w;
        const float area1 = (px1 - px0) * (py1 - py0);

        #pragma unroll
        for (int t = 0; t < NT; ++t) {
            const float prob = __expf(row[slab[t]]) * rs;

            const float4 tc = stbc[t];
            const float l1 = fabsf(pb.x - tc.x) + fabsf(pb.y - tc.y)
                           + fabsf(pb.z - tc.z) + fabsf(pb.w - tc.w);

            const float4 tx = stbx[t];
            const float ltx = fmaxf(px0, tx.x), lty = fmaxf(py0, tx.y);
            const float rbx = fminf(px1, tx.z), rby = fminf(py1, tx.w);
            const float iw = fmaxf(rbx - ltx, 0.0f), ih = fmaxf(rby - lty, 0.0f);
            const float inter = iw * ih;
            const float uni = area1 + sarea[t] - inter;

            const float elx = fminf(px0, tx.x), ely = fminf(py0, tx.y);
            const float erx = fmaxf(px1, tx.z), ery = fmaxf(py1, tx.w);
            const float ew = fmaxf(erx - elx, 0.0f), eh = fmaxf(ery - ely, 0.0f);
            const float areae = ew * eh;

            // giou = inter/uni - (areae-uni)/areae, single reciprocal
            const float giou = __fdividef(inter * areae - uni * (areae - uni),
                                          uni * areae);

            res[t] = -prob + 5.0f * l1 - 2.0f * giou;
        }
    }
    __syncthreads();

    if (q < NQ) {
        #pragma unroll
        for (int t = 0; t < NT; ++t) sh[q * 21 + t] = res[t];
    }
    __syncthreads();

    float* cbase = cost + (size_t)inst * (NQ * NT);
    #pragma unroll 4
    for (int i = tid; i < NQ * NT; i += 128) {
        const int q2 = i / NT, t2 = i - q2 * NT;
        cbase[i] = sh[q2 * 21 + t2];
    }
}

// ---------------------------------------------------------------------------
// Kernel B: Jacobi auction, register-state version.
//   - group-cooperative top-2 scan (adaptive gsize, 4-chain ILP)
//   - winner resolution via match_any + reduce_max (bid > 0 so float bits
//     order as uint) + ballot/ffs for min-bidder-id tie-break
//   - evictions via a second match_any against winner mask
//   - ONE __syncwarp per round (price visibility)
// ---------------------------------------------------------------------------
__global__ void auction_kernel(const float* __restrict__ cost,
                               float* __restrict__ out_pred,
                               float* __restrict__ out_tgt)
{
    const int inst = blockIdx.x;
    const int t = threadIdx.x;

    __shared__ float ben[NT * NQP];
    __shared__ float price[NQ];

    const float* c = cost + (size_t)inst * (NQ * NT);

    float mx = -INFINITY, mn = INFINITY;
    for (int i = t; i < NQ * NT; i += 32) {
        const int qq = i / NT, tt = i - qq * NT;
        const float v = -c[i];
        ben[tt * NQP + qq] = v;
        mx = fmaxf(mx, v);
        mn = fminf(mn, v);
    }
    for (int i = t; i < NQ; i += 32) price[i] = 0.0f;

    #pragma unroll
    for (int o = 16; o > 0; o >>= 1) {
        mx = fmaxf(mx, __shfl_xor_sync(FULLW, mx, o));
        mn = fminf(mn, __shfl_xor_sync(FULLW, mn, o));
    }
    const float eps = (mx - mn + 1e-06f) / 1000.0f;

    int myobj = (t < NT) ? -1 : 0;       // lanes >= NT永 assigned dummy
    __syncwarp();

    for (int it = 0; it < 20000; ++it) {
        const bool un = (t < NT) && (myobj < 0);
        const unsigned mask = __ballot_sync(FULLW, un);
        if (!mask) break;
        const int u = __popc(mask);

        const int shift = 31 - __clz(32 / u);     // log2(gsize)
        const int gsize = 1 << shift;
        const int grp = t >> shift;
        const int lig = t & (gsize - 1);
        const bool live = (grp < u);
        const int trow = live ? (int)__fns(mask, 0, grp + 1) : 0;

        // --- 4-chain ILP top-2 scan over this group's bidder row ---
        float s1[4], s2[4];
        int   si[4];
        #pragma unroll
        for (int j = 0; j < 4; ++j) { s1[j] = -INFINITY; s2[j] = -INFINITY; si[j] = 0; }
        const float* br = &ben[trow * NQP];
        int qq = lig;
        const int stride4 = gsize << 2;
        for (; qq + 3 * gsize < NQ; qq += stride4) {
            #pragma unroll
            for (int j = 0; j < 4; ++j) {
                const int qj = qq + j * gsize;
                const float v = br[qj] - price[qj];
                if (v > s1[j]) { s2[j] = s1[j]; s1[j] = v; si[j] = qj; }
                else if (v > s2[j]) { s2[j] = v; }
            }
        }
        for (; qq < NQ; qq += gsize) {
            const float v = br[qq] - price[qq];
            if (v > s1[0]) { s2[0] = s1[0]; s1[0] = v; si[0] = qq; }
            else if (v > s2[0]) { s2[0] = v; }
        }
        merge2(s1[0], si[0], s2[0], s1[1], si[1], s2[1]);
        merge2(s1[2], si[2], s2[2], s1[3], si[3], s2[3]);
        merge2(s1[0], si[0], s2[0], s1[2], si[2], s2[2]);
        float b1 = s1[0], b2 = s2[0];
        int   i1 = si[0];

        // butterfly: ALL group lanes end with the group result
        for (int o = gsize >> 1; o > 0; o >>= 1) {
            const float ob1 = __shfl_xor_sync(FULLW, b1, o);
            const int   oi1 = __shfl_xor_sync(FULLW, i1, o);
            const float ob2 = __shfl_xor_sync(FULLW, b2, o);
            merge2(b1, i1, b2, ob1, oi1, ob2);
        }
        const float bidv = price[i1] + (b1 - b2) + eps;   // > 0 always

        // route group result to the bidder's lane (bidder rank j -> leader j*gsize)
        const int rank = __popc(mask & ((1u << t) - 1u));
        const int src = un ? (rank << shift) : 0;
        const float mybid = __shfl_sync(FULLW, bidv, src);
        const int   myq   = __shfl_sync(FULLW, i1,   src);

        // --- winner per object: max bid, min bidder id on tie ---
        const unsigned key = un ? __float_as_uint(mybid) : 0u;
        const int objv = un ? myq : (256 + t);
        const unsigned grpm = __match_any_sync(FULLW, objv);
        const unsigned maxb = __reduce_max_sync(grpm, key);
        const bool cand = un && (key == maxb);
        const unsigned wb = __ballot_sync(FULLW, cand);
        const bool winf = cand && (t == (__ffs(grpm & wb) - 1));
        const unsigned wmask = __ballot_sync(FULLW, winf);

        // --- eviction: assigned lane whose object was won this round ---
        const bool assigned = (t < NT) && (myobj >= 0);
        const int objv2 = winf ? myq : (assigned ? myobj : (256 + t));
        const unsigned g2 = __match_any_sync(FULLW, objv2);
        const bool evict = assigned && ((g2 & wmask) != 0u);

        myobj = winf ? myq : (evict ? -1 : myobj);
        if (winf) price[myq] = mybid;
        __syncwarp();
    }

    // stable argsort of obj_of over bidders; gather via shuffles
    if (true) {
        const int v = myobj;
        int rankv = 0;
        #pragma unroll
        for (int t3 = 0; t3 < NT; ++t3) {
            const int v2 = __shfl_sync(FULLW, myobj, t3);
            rankv += (v2 < v) || (v2 == v && t3 < t);
        }
        if (t < NT) {
            out_pred[(size_t)inst * NT + rankv] = (float)v;
            out_tgt [(size_t)inst * NT + rankv] = (float)t;
        }
    }
}

// ---------------------------------------------------------------------------
extern "C" void kernel_launch(void* const* d_in, const int* in_sizes, int n_in,
                              void* d_out, int out_size)
{
    const float* logits  = (const float*)d_in[0];  // (64, 3600, 92)
    const float* pboxes  = (const float*)d_in[1];  // (64, 3600, 4)
    const int*   tlabels = (const int*)  d_in[2];  // (36, 64, 20)
    const float* tboxes  = (const float*)d_in[3];  // (36, 64, 20, 4)

    float* out  = (float*)d_out;
    float* cost = out;
    float* pidx = out + COST_ELEMS;
    float* tidx = out + COST_ELEMS + IDX_ELEMS;

    cost_kernel<<<NINST, 128>>>(logits, pboxes, tlabels, tboxes, cost);
    auction_kernel<<<NINST, 32>>>(cost, pidx, tidx);
}

// round 7
// speedup vs baseline: 1.5304x; 1.5304x over previous
#include <cuda_runtime.h>
#include <math.h>

// Problem constants
#define NB 64
#define NF 36
#define NQ 100
#define NQP 101                         // auction smem stride (conflict-free)
#define NT 20
#define NC 92
#define NQUERY (NB * NF * NQ)          // 230400
#define NINST  (NB * NF)               // 2304
#define COST_ELEMS (NQUERY * NT)       // 4608000
#define IDX_ELEMS  (NINST * NT)        // 46080

// ---------------------------------------------------------------------------
// Kernel A: cost tensor. Block = one (b,f) frame; thread q computes query q
// reading its own logit row directly from gmem (no smem staging). Output is
// coalesced via a small smem buffer (stride 21, conflict-free).
// ---------------------------------------------------------------------------
__global__ __launch_bounds__(128) void cost_kernel(
        const float* __restrict__ logits,
        const float* __restrict__ pboxes,
        const int*   __restrict__ tlabels,
        const float* __restrict__ tboxes,
        float* __restrict__ cost)
{
    const int inst = blockIdx.x;          // b*36 + f
    const int b = inst / NF;
    const int f = inst - b * NF;
    const int tid = threadIdx.x;

    __shared__ float  sout[NQ * 21];      // 8.4 KB output staging
    __shared__ float4 stbc[NT];           // target cxcywh
    __shared__ float4 stbx[NT];           // target xyxy
    __shared__ float  sarea[NT];
    __shared__ int    slab[NT];

    if (tid < NT) {
        const size_t tb_ = (size_t)(f * NB + b) * NT + tid;
        const float4 tb = ((const float4*)tboxes)[tb_];
        stbc[tid] = tb;
        const float x0 = tb.x - 0.5f * tb.z, y0 = tb.y - 0.5f * tb.w;
        const float x1 = tb.x + 0.5f * tb.z, y1 = tb.y + 0.5f * tb.w;
        stbx[tid]  = make_float4(x0, y0, x1, y1);
        sarea[tid] = (x1 - x0) * (y1 - y0);
        slab[tid]  = tlabels[tb_];
    }
    __syncthreads();

    const int q = tid;
    if (q < NQ) {
        const float* row = logits + ((size_t)b * (NF * NQ) + f * NQ + q) * NC;
        const float4* r4 = (const float4*)row;

        // softmax denominator: 23 contiguous float4 loads (row is L1-resident)
        float s = 0.0f;
        #pragma unroll
        for (int i = 0; i < 23; ++i) {
            const float4 v = r4[i];
            s += (__expf(v.x) + __expf(v.y)) + (__expf(v.z) + __expf(v.w));
        }
        const float rs = __fdividef(1.0f, s);

        const float4 pb = *(const float4*)(pboxes + ((size_t)b * (NF * NQ) + f * NQ + q) * 4);
        const float px0 = pb.x - 0.5f * pb.z;
        const float py0 = pb.y - 0.5f * pb.w;
        const float px1 = pb.x + 0.5f * pb.z;
        const float py1 = pb.y + 0.5f * pb.w;
        const float area1 = (px1 - px0) * (py1 - py0);

        #pragma unroll
        for (int t = 0; t < NT; ++t) {
            const float prob = __expf(__ldg(row + slab[t])) * rs;   // L1 hit

            const float4 tc = stbc[t];
            const float l1 = fabsf(pb.x - tc.x) + fabsf(pb.y - tc.y)
                           + fabsf(pb.z - tc.z) + fabsf(pb.w - tc.w);

            const float4 tx = stbx[t];
            const float ltx = fmaxf(px0, tx.x), lty = fmaxf(py0, tx.y);
            const float rbx = fminf(px1, tx.z), rby = fminf(py1, tx.w);
            const float iw = fmaxf(rbx - ltx, 0.0f), ih = fmaxf(rby - lty, 0.0f);
            const float inter = iw * ih;
            const float uni = area1 + sarea[t] - inter;

            const float elx = fminf(px0, tx.x), ely = fminf(py0, tx.y);
            const float erx = fmaxf(px1, tx.z), ery = fmaxf(py1, tx.w);
            const float ew = fmaxf(erx - elx, 0.0f), eh = fmaxf(ery - ely, 0.0f);
            const float areae = ew * eh;

            // giou = inter/uni - (areae-uni)/areae with a single reciprocal
            const float giou = __fdividef(inter * areae - uni * (areae - uni),
                                          uni * areae);

            sout[q * 21 + t] = -prob + 5.0f * l1 - 2.0f * giou;
        }
    }
    __syncthreads();

    float* cbase = cost + (size_t)inst * (NQ * NT);
    #pragma unroll 4
    for (int i = tid; i < NQ * NT; i += 128) {
        const int q2 = i / NT, t2 = i - q2 * NT;
        cbase[i] = sout[q2 * 21 + t2];
    }
}

// ---------------------------------------------------------------------------
// Kernel B: synchronous Jacobi auction with adaptive group-cooperative top-2.
// (exact R3 version — best measured: 27.6 us)
// ---------------------------------------------------------------------------
__global__ void auction_kernel(const float* __restrict__ cost,
                               float* __restrict__ out_pred,
                               float* __restrict__ out_tgt)
{
    const int inst = blockIdx.x;
    const int t = threadIdx.x;

    __shared__ float ben[NT * NQP];
    __shared__ float price[NQ];
    __shared__ int   owner[NQ];
    __shared__ int   obj_of[NT];
    __shared__ float sbid[NT];
    __shared__ int   sobj[NT];
    __shared__ int   blist[NT];

    const float* c = cost + (size_t)inst * (NQ * NT);

    float mx = -INFINITY, mn = INFINITY;
    for (int i = t; i < NQ * NT; i += 32) {
        const int qq = i / NT, tt = i - qq * NT;
        const float v = -c[i];
        ben[tt * NQP + qq] = v;
        mx = fmaxf(mx, v);
        mn = fminf(mn, v);
    }
    for (int i = t; i < NQ; i += 32) { price[i] = 0.0f; owner[i] = -1; }
    if (t < NT) obj_of[t] = -1;

    #pragma unroll
    for (int o = 16; o > 0; o >>= 1) {
        mx = fmaxf(mx, __shfl_xor_sync(0xffffffffu, mx, o));
        mn = fminf(mn, __shfl_xor_sync(0xffffffffu, mn, o));
    }
    const float eps = (mx - mn + 1e-06f) / 1000.0f;
    __syncwarp();

    for (int it = 0; it < 20000; ++it) {
        const bool un = (t < NT) && (obj_of[t] < 0);
        const unsigned mask = __ballot_sync(0xffffffffu, un);
        if (!mask) break;
        const int u = __popc(mask);

        if (un) blist[__popc(mask & ((1u << t) - 1u))] = t;
        __syncwarp();

        const int gp = 32 / u;
        const int gsize = 1 << (31 - __clz(gp));
        const int grp = t / gsize;
        const int lig = t - grp * gsize;
        const bool live = (grp < u);
        const int t2 = blist[live ? grp : 0];

        float b1 = -INFINITY, b2 = -INFINITY;
        int i1 = 0;
        const float* br = &ben[t2 * NQP];
        for (int q = lig; q < NQ; q += gsize) {
            const float v = br[q] - price[q];
            if (v > b1) { b2 = b1; b1 = v; i1 = q; }
            else if (v > b2) { b2 = v; }
        }
        for (int o = gsize >> 1; o > 0; o >>= 1) {
            const float ob1 = __shfl_xor_sync(0xffffffffu, b1, o);
            const int   oi1 = __shfl_xor_sync(0xffffffffu, i1, o);
            const float ob2 = __shfl_xor_sync(0xffffffffu, b2, o);
            const bool aw = (b1 > ob1) || (b1 == ob1 && i1 < oi1);
            const float lose = aw ? ob1 : b1;
            b2 = fmaxf(lose, fmaxf(b2, ob2));
            b1 = aw ? b1 : ob1;
            i1 = aw ? i1 : oi1;
        }
        if (live && lig == 0) {
            sbid[t2] = price[i1] + (b1 - b2) + eps;
            sobj[t2] = i1;
        }
        __syncwarp();

        bool winf = false;
        int myq = -1;
        if (un) {
            myq = sobj[t];
            const float mybid = sbid[t];
            winf = true;
            for (unsigned mm = mask & ~(1u << t); mm; mm &= mm - 1u) {
                const int t3 = __ffs(mm) - 1;
                if (sobj[t3] == myq) {
                    const float ob = sbid[t3];
                    if (ob > mybid || (ob == mybid && t3 < t)) winf = false;
                }
            }
        }
        __syncwarp();

        int old = -1;
        if (winf) old = owner[myq];
        __syncwarp();
        if (winf && old >= 0) obj_of[old] = -1;
        __syncwarp();
        if (winf) {
            obj_of[t] = myq;
            price[myq] = sbid[t];
            owner[myq] = t;
        }
        __syncwarp();
    }

    if (t < NT) {
        const int v = obj_of[t];
        int rank = 0;
        #pragma unroll
        for (int t3 = 0; t3 < NT; ++t3) {
            const int v2 = obj_of[t3];
            rank += (v2 < v) || (v2 == v && t3 < t);
        }
        out_pred[(size_t)inst * NT + rank] = (float)v;
        out_tgt [(size_t)inst * NT + rank] = (float)t;
    }
}

// ---------------------------------------------------------------------------
extern "C" void kernel_launch(void* const* d_in, const int* in_sizes, int n_in,
                              void* d_out, int out_size)
{
    const float* logits  = (const float*)d_in[0];  // (64, 3600, 92)
    const float* pboxes  = (const float*)d_in[1];  // (64, 3600, 4)
    const int*   tlabels = (const int*)  d_in[2];  // (36, 64, 20)
    const float* tboxes  = (const float*)d_in[3];  // (36, 64, 20, 4)

    float* out  = (float*)d_out;
    float* cost = out;
    float* pidx = out + COST_ELEMS;
    float* tidx = out + COST_ELEMS + IDX_ELEMS;

    cost_kernel<<<NINST, 128>>>(logits, pboxes, tlabels, tboxes, cost);
    auction_kernel<<<NINST, 32>>>(cost, pidx, tidx);
}